// round 2
// baseline (speedup 1.0000x reference)
#include <cuda_runtime.h>

// Fused: gather(features2 via topk) ++ features1 -> [128 rows x 128]
//        -> ELU(X@W1+b1) -> ELU(H@W2+b2) -> distance-weighted sum over 16 nbrs.
// One block = 8 queries = 128 rows. Two 128x128x128 fp32 GEMMs per block.

namespace {
constexpr int kN1      = 50000;
constexpr int kNN      = 16;
constexpr int kQPB     = 8;               // queries per block
constexpr int kROWS    = kQPB * kNN;      // 128
constexpr int kK       = 128;             // hidden/contraction dim
constexpr int kKC      = 32;              // K-chunk staged in smem
constexpr int kThreads = 256;
constexpr int kSmemFloats = 128 * 128     // XsT (transposed, swizzled input/hidden)
                          + kKC * 128     // W chunk (reused as reduction buffer)
                          + 128           // roww (per-row weight)
                          + 128;          // rowg (gather indices, as int)
}

__device__ __forceinline__ float elu_f(float x) {
    return x > 0.0f ? x : expm1f(x);
}

// Swizzle: logical (k, r) -> XsT[k*128 + (r ^ (((k>>3)&7)<<2))]
// Keeps float4 groups contiguous (XOR only touches bits 2..4 of r) and makes the
// transposed ELU write-back spread across banks instead of a 16-way conflict.

__global__ void __launch_bounds__(kThreads, 2)
fused_knn_mlp_kernel(const float* __restrict__ f1, const float* __restrict__ f2,
                     const float* __restrict__ x1, const float* __restrict__ x2,
                     const void* __restrict__ topk,
                     const float* __restrict__ W1, const float* __restrict__ b1,
                     const float* __restrict__ W2, const float* __restrict__ b2,
                     const float* __restrict__ radius,
                     float* __restrict__ out)
{
    extern __shared__ float smem[];
    float* XsT  = smem;                       // [128][128] (k-major, swizzled)
    float* Wc   = XsT + 128 * 128;            // [kKC][128]
    float* roww = Wc + kKC * 128;             // [128]
    int*   rowg = (int*)(roww + 128);         // [128]
    __shared__ int s_is64;

    const int tid   = threadIdx.x;
    const int qbase = blockIdx.x * kQPB;

    // ---- detect topk element width (int64 vs int32) ----
    // If data is little-endian int64 with values < 2^31, every odd int32 word is 0.
    // For int32 data, 32 random values in [0,50000) are essentially never all zero.
    if (tid < 32) {
        const int* t32 = (const int*)topk;
        unsigned m = __ballot_sync(0xFFFFFFFFu, t32[2 * tid + 1] != 0);
        if (tid == 0) s_is64 = (m == 0u) ? 1 : 0;
    }
    __syncthreads();
    const bool is64 = (s_is64 != 0);

    // ---- per-row metadata: gather index + distance weight ----
    if (tid < kROWS) {
        const int q  = qbase + (tid >> 4);
        const int kk = tid & 15;
        int gi;
        if (is64) gi = (int)((const long long*)topk)[q * kNN + kk];
        else      gi = ((const int*)topk)[q * kNN + kk];
        const float dx = x2[gi * 3 + 0] - x1[q * 3 + 0];
        const float dy = x2[gi * 3 + 1] - x1[q * 3 + 1];
        const float dz = x2[gi * 3 + 2] - x1[q * 3 + 2];
        const float d2 = dx * dx + dy * dy + dz * dz;
        const float r  = radius[0];
        const float w  = expf(-d2 / (2.0f * r * r));
        roww[tid] = (gi == 0) ? 0.0f : w;
        rowg[tid] = gi;
    }
    __syncthreads();

    // ---- build XsT: X[r][0:64]=features2[topk], X[r][64:128]=features1[q] ----
    for (int m = tid; m < kROWS * 32; m += kThreads) {
        const int r  = m >> 5;      // logical row
        const int c4 = m & 31;      // float4 column slot (32 per row)
        float4 v = (c4 < 16)
            ? ((const float4*)f2)[(size_t)rowg[r] * 16 + c4]
            : ((const float4*)f1)[(size_t)(qbase + (r >> 4)) * 16 + (c4 - 16)];
        const int k0 = c4 * 4;
        const float* vp = (const float*)&v;
        #pragma unroll
        for (int j = 0; j < 4; j++) {
            const int k  = k0 + j;
            const int pc = r ^ (((k >> 3) & 7) << 2);
            XsT[k * 128 + pc] = vp[j];
        }
    }
    __syncthreads();

    const int ty = tid >> 4;   // 0..15 -> row tile
    const int tx = tid & 15;   // 0..15 -> col tile

    float acc[8][8];
    #pragma unroll
    for (int i = 0; i < 8; i++)
        #pragma unroll
        for (int j = 0; j < 8; j++) acc[i][j] = 0.0f;

    const float* Wl = W1;
    #pragma unroll 1
    for (int layer = 0; layer < 2; ++layer) {
        // ---- GEMM: acc[r][c] += XsT[k][r] * Wl[k][c], K = 128 in chunks ----
        #pragma unroll 1
        for (int ch = 0; ch < kK / kKC; ++ch) {
            const float4* Wg = (const float4*)(Wl + ch * kKC * 128);
            #pragma unroll
            for (int i = 0; i < (kKC * 128 / 4) / kThreads; i++)
                ((float4*)Wc)[tid + i * kThreads] = Wg[tid + i * kThreads];
            __syncthreads();

            #pragma unroll 8
            for (int kk = 0; kk < kKC; kk++) {
                const int k  = ch * kKC + kk;
                const int sw = ((k >> 3) & 7) << 2;
                const float4 a0 = *(const float4*)&XsT[k * 128 + ((ty * 8)     ^ sw)];
                const float4 a1 = *(const float4*)&XsT[k * 128 + ((ty * 8 + 4) ^ sw)];
                const float4 w0 = *(const float4*)&Wc[kk * 128 + tx * 8];
                const float4 w1 = *(const float4*)&Wc[kk * 128 + tx * 8 + 4];
                const float a[8] = {a0.x, a0.y, a0.z, a0.w, a1.x, a1.y, a1.z, a1.w};
                const float b[8] = {w0.x, w0.y, w0.z, w0.w, w1.x, w1.y, w1.z, w1.w};
                #pragma unroll
                for (int i = 0; i < 8; i++)
                    #pragma unroll
                    for (int j = 0; j < 8; j++)
                        acc[i][j] = fmaf(a[i], b[j], acc[i][j]);
            }
            __syncthreads();
        }

        if (layer == 0) {
            // bias + ELU, write back transposed into XsT for layer 2
            float bias[8];
            #pragma unroll
            for (int j = 0; j < 8; j++) bias[j] = __ldg(&b1[tx * 8 + j]);
            #pragma unroll
            for (int i = 0; i < 8; i++) {
                const int r = ty * 8 + i;
                #pragma unroll
                for (int j = 0; j < 8; j++) {
                    const float v  = elu_f(acc[i][j] + bias[j]);
                    const int   k  = tx * 8 + j;
                    const int   pc = r ^ (((k >> 3) & 7) << 2);
                    XsT[k * 128 + pc] = v;
                    acc[i][j] = 0.0f;
                }
            }
            __syncthreads();
            Wl = W2;
        }
    }

    // ---- epilogue: bias2 + ELU + weighted sum over 16 neighbor rows ----
    float bias2[8], s[8];
    #pragma unroll
    for (int j = 0; j < 8; j++) { bias2[j] = __ldg(&b2[tx * 8 + j]); s[j] = 0.0f; }
    #pragma unroll
    for (int i = 0; i < 8; i++) {
        const float w = roww[ty * 8 + i];
        #pragma unroll
        for (int j = 0; j < 8; j++)
            s[j] = fmaf(w, elu_f(acc[i][j] + bias2[j]), s[j]);
    }

    // each query spans 2 ty values (16 rows); reduce the odd-ty half into even-ty
    float* red = Wc;   // reuse W chunk buffer (8 queries x 128 cols)
    const int q = ty >> 1;
    if (ty & 1) {
        float4* rp = (float4*)&red[q * 128 + tx * 8];
        rp[0] = make_float4(s[0], s[1], s[2], s[3]);
        rp[1] = make_float4(s[4], s[5], s[6], s[7]);
    }
    __syncthreads();
    if (!(ty & 1)) {
        const float4* rp = (const float4*)&red[q * 128 + tx * 8];
        const float4 r0 = rp[0], r1 = rp[1];
        float4 o0 = make_float4(s[0] + r0.x, s[1] + r0.y, s[2] + r0.z, s[3] + r0.w);
        float4 o1 = make_float4(s[4] + r1.x, s[5] + r1.y, s[6] + r1.z, s[7] + r1.w);
        float4* op = (float4*)&out[(size_t)(qbase + q) * 128 + tx * 8];
        op[0] = o0;
        op[1] = o1;
    }
}

extern "C" void kernel_launch(void* const* d_in, const int* in_sizes, int n_in,
                              void* d_out, int out_size) {
    const float* f1     = (const float*)d_in[0];   // features1 [N1, 64]
    const float* f2     = (const float*)d_in[1];   // features2 [N2, 64]
    const float* x1     = (const float*)d_in[2];   // [N1, 3]
    const float* x2     = (const float*)d_in[3];   // [N2, 3]
    // d_in[4], d_in[5] (nuv1, nuv2) unused by the reference math
    const void*  topk   = d_in[6];                 // [N1, 16] int32 or int64
    const float* W1     = (const float*)d_in[7];   // [128, 128]
    const float* b1     = (const float*)d_in[8];   // [128]
    const float* W2     = (const float*)d_in[9];   // [128, 128]
    const float* b2     = (const float*)d_in[10];  // [128]
    const float* radius = (const float*)d_in[11];  // [1]
    float* out = (float*)d_out;

    const size_t smem_bytes = (size_t)kSmemFloats * sizeof(float);  // 82944 B
    cudaFuncSetAttribute(fused_knn_mlp_kernel,
                         cudaFuncAttributeMaxDynamicSharedMemorySize,
                         (int)smem_bytes);
    fused_knn_mlp_kernel<<<kN1 / kQPB, kThreads, smem_bytes>>>(
        f1, f2, x1, x2, topk, W1, b1, W2, b2, radius, out);
}

// round 4
// speedup vs baseline: 1.5792x; 1.5792x over previous
#include <cuda_runtime.h>
#include <cuda_bf16.h>
#include <cstdint>

// Tensor-core version using baseline-PTX warp MMAs (mma.sync m16n8k16 bf16,
// valid on plain sm_103 target — tcgen05 is rejected by the harness's PTX stage).
//   X[128x128] = [features2[topk] | features1]  (8 queries x 16 nbrs = 128 rows)
//   H = ELU(X@W1+b1); Y = ELU(H@W2+b2); out[q] = sum_k w[q,k] * Y[q*16+k]
// Each GEMM: D(fp32) = Ah*Bh + Ah*Bl + Al*Bh  (bf16 hi/lo split)

namespace {
constexpr int kN1      = 50000;
constexpr int kNN      = 16;
constexpr int kQPB     = 8;
constexpr int kTiles   = kN1 / kQPB;   // 6250
constexpr int kThreads = 256;
constexpr int kGrid    = 148;

// SMEM byte offsets
constexpr int SM_ROWW  = 0;                   // 128 f32
constexpr int SM_ROWG  = 512;                 // 128 i32
constexpr int SM_B1    = 1024;                // 128 f32
constexpr int SM_B2    = 1536;                // 128 f32
constexpr int SM_X     = 4096;                // union region
constexpr int SM_XHI   = SM_X;                // 32768 B bf16 swizzled [row][k]
constexpr int SM_XLO   = SM_X + 32768;        // 32768 B
constexpr int SM_SCR   = SM_X;                // fp32 scratch 128 x 132 (67584 B)
constexpr int SM_XSZ   = 69632;               // union size (padded)
constexpr int SM_W     = SM_X + SM_XSZ;       // 73728
constexpr int SM_WSZ   = 32768;               // per W buffer [n][k] bf16 swizzled
constexpr int SM_TOTAL = SM_W + 4 * SM_WSZ;   // 204800 B
}

// Pre-split, pre-transposed, pre-swizzled weights: [W1hi, W1lo, W2hi, W2lo]
__device__ __align__(16) unsigned char g_Wsplit[4 * SM_WSZ];

// Swizzled byte offset for [row][k] bf16 tiles (256 B rows, XOR on 16B groups).
// ldmatrix: 8 rows at the same k-group hit 8 distinct 16B banks.
__device__ __forceinline__ uint32_t soff(int r, int k) {
    return (uint32_t)(r * 256 + ((((k >> 3) ^ (r & 7)) & 15) << 4) + (k & 7) * 2);
}

__device__ __forceinline__ uint32_t smem_u32(const void* p) {
    uint32_t a;
    asm("{ .reg .u64 t; cvta.to.shared.u64 t, %1; cvt.u32.u64 %0, t; }"
        : "=r"(a) : "l"(p));
    return a;
}
__device__ __forceinline__ void ldsm_x4(uint32_t* r, uint32_t addr) {
    asm volatile("ldmatrix.sync.aligned.m8n8.x4.shared.b16 {%0,%1,%2,%3}, [%4];"
                 : "=r"(r[0]), "=r"(r[1]), "=r"(r[2]), "=r"(r[3]) : "r"(addr));
}
__device__ __forceinline__ void mma16816(float* d, const uint32_t* a,
                                         const uint32_t* b) {
    asm volatile(
        "mma.sync.aligned.m16n8k16.row.col.f32.bf16.bf16.f32 "
        "{%0,%1,%2,%3}, {%4,%5,%6,%7}, {%8,%9}, {%0,%1,%2,%3};"
        : "+f"(d[0]), "+f"(d[1]), "+f"(d[2]), "+f"(d[3])
        : "r"(a[0]), "r"(a[1]), "r"(a[2]), "r"(a[3]), "r"(b[0]), "r"(b[1]));
}
__device__ __forceinline__ float elu_f(float x) { return x > 0.0f ? x : expm1f(x); }

__device__ __forceinline__ void split_bf16(float a, float b, uint32_t& hi,
                                           uint32_t& lo) {
    const __nv_bfloat16 ah = __float2bfloat16(a);
    const __nv_bfloat16 bh = __float2bfloat16(b);
    __nv_bfloat162 h2 = __halves2bfloat162(ah, bh);
    __nv_bfloat162 l2 = __halves2bfloat162(
        __float2bfloat16(a - __bfloat162float(ah)),
        __float2bfloat16(b - __bfloat162float(bh)));
    hi = *(uint32_t*)&h2;
    lo = *(uint32_t*)&l2;
}

// ---------------- W prep kernel ----------------
__global__ void prep_w_kernel(const float* __restrict__ W1,
                              const float* __restrict__ W2) {
    int idx = blockIdx.x * blockDim.x + threadIdx.x;   // 0 .. 32767
    if (idx >= 2 * 128 * 128) return;
    int l = idx >> 14;
    int e = idx & 16383;
    int n = e >> 7;      // output channel (B row)
    int k = e & 127;     // contraction
    const float* W = l ? W2 : W1;
    float v = W[k * 128 + n];                       // B[n][k] = W[k][n]
    __nv_bfloat16 h  = __float2bfloat16(v);
    __nv_bfloat16 lo = __float2bfloat16(v - __bfloat162float(h));
    uint32_t o = soff(n, k);
    *(__nv_bfloat16*)(g_Wsplit + (2 * l + 0) * SM_WSZ + o) = h;
    *(__nv_bfloat16*)(g_Wsplit + (2 * l + 1) * SM_WSZ + o) = lo;
}

// ---------------- main persistent kernel ----------------
__global__ void __launch_bounds__(kThreads, 1)
fused_mma_kernel(const float* __restrict__ f1, const float* __restrict__ f2,
                 const float* __restrict__ x1, const float* __restrict__ x2,
                 const void* __restrict__ topk,
                 const float* __restrict__ b1, const float* __restrict__ b2,
                 const float* __restrict__ radius, float* __restrict__ out)
{
    extern __shared__ char sm[];
    const uint32_t smb = smem_u32(sm);
    const int tid  = threadIdx.x;
    const int wid  = tid >> 5;
    const int lane = tid & 31;
    __shared__ int s_is64;

    // stage split weights into SMEM once (layout-identical byte copy)
    {
        const float4* src = (const float4*)g_Wsplit;
        float4* dst = (float4*)(sm + SM_W);
        #pragma unroll
        for (int i = 0; i < 32; i++) dst[tid + i * 256] = src[tid + i * 256];
    }
    if (tid < 128) {
        ((float*)(sm + SM_B1))[tid] = b1[tid];
        ((float*)(sm + SM_B2))[tid] = b2[tid];
    }
    if (tid < 32) {
        const int* t32 = (const int*)topk;
        unsigned m = __ballot_sync(0xFFFFFFFFu, t32[2 * tid + 1] != 0);
        if (tid == 0) s_is64 = (m == 0u) ? 1 : 0;
    }
    __syncthreads();

    const bool  is64 = (s_is64 != 0);
    const float r    = radius[0];
    const float nid  = -1.0f / (2.0f * r * r);

    const int wrow = (wid & 3) * 32;   // warp tile rows [wrow, wrow+32)
    const int wcol = (wid >> 2) * 64;  // warp tile cols [wcol, wcol+64)
    const int mat  = lane >> 3;        // ldmatrix sub-matrix index
    const int mrow = lane & 7;

    const uint32_t xh = smb + SM_XHI;
    const uint32_t xl = smb + SM_XLO;

    for (int tile = blockIdx.x; tile < kTiles; tile += gridDim.x) {
        const int qbase = tile * kQPB;

        // ---- per-row metadata ----
        if (tid < 128) {
            const int q  = qbase + (tid >> 4);
            const int kk = tid & 15;
            int gi = is64 ? (int)((const long long*)topk)[q * kNN + kk]
                          : ((const int*)topk)[q * kNN + kk];
            const float dx = x2[gi * 3 + 0] - x1[q * 3 + 0];
            const float dy = x2[gi * 3 + 1] - x1[q * 3 + 1];
            const float dz = x2[gi * 3 + 2] - x1[q * 3 + 2];
            const float w  = expf(nid * (dx * dx + dy * dy + dz * dz));
            ((float*)(sm + SM_ROWW))[tid] = (gi == 0) ? 0.0f : w;
            ((int*)(sm + SM_ROWG))[tid]   = gi;
        }
        __syncthreads();

        // ---- gather + bf16 split into Xhi/Xlo ----
        {
            const int* rowg = (const int*)(sm + SM_ROWG);
            #pragma unroll
            for (int it = 0; it < 8; ++it) {
                const int m  = tid + it * 256;  // 0..2047
                const int rr = m >> 4;          // row
                const int g  = m & 15;          // 8-float group (k0 = g*8)
                const float4* srcp = (g < 8)
                    ? (const float4*)(f2 + (size_t)rowg[rr] * 64) + g * 2
                    : (const float4*)(f1 + (size_t)(qbase + (rr >> 4)) * 64) + (g - 8) * 2;
                const float4 v0 = srcp[0], v1 = srcp[1];
                const float v[8] = {v0.x, v0.y, v0.z, v0.w, v1.x, v1.y, v1.z, v1.w};
                uint4 hi4, lo4;
                uint32_t* hp = (uint32_t*)&hi4;
                uint32_t* lp = (uint32_t*)&lo4;
                #pragma unroll
                for (int j = 0; j < 4; j++)
                    split_bf16(v[2 * j], v[2 * j + 1], hp[j], lp[j]);
                const uint32_t o = soff(rr, g * 8);
                *(uint4*)(sm + SM_XHI + o) = hi4;
                *(uint4*)(sm + SM_XLO + o) = lo4;
            }
        }
        __syncthreads();

        float acc[2][8][4];
        #pragma unroll
        for (int i = 0; i < 2; i++)
            #pragma unroll
            for (int j = 0; j < 8; j++)
                #pragma unroll
                for (int e = 0; e < 4; e++) acc[i][j][e] = 0.0f;

        #pragma unroll 1
        for (int layer = 0; layer < 2; ++layer) {
            const uint32_t wh = smb + SM_W + (2 * layer + 0) * SM_WSZ;
            const uint32_t wl = smb + SM_W + (2 * layer + 1) * SM_WSZ;

            #pragma unroll 1
            for (int ks = 0; ks < 8; ++ks) {
                // A fragments: 2 m-tiles, hi & lo
                uint32_t ah[2][4], al[2][4];
                #pragma unroll
                for (int mt = 0; mt < 2; mt++) {
                    const int row = wrow + mt * 16 + (mat & 1) * 8 + mrow;
                    const int kk  = ks * 16 + (mat >> 1) * 8;
                    const uint32_t o = soff(row, kk);
                    ldsm_x4(ah[mt], xh + o);
                    ldsm_x4(al[mt], xl + o);
                }
                // 4 n-tile pairs
                #pragma unroll
                for (int pr = 0; pr < 4; pr++) {
                    const int n  = wcol + pr * 16 + (mat >> 1) * 8 + mrow;
                    const int kk = ks * 16 + (mat & 1) * 8;
                    const uint32_t o = soff(n, kk);
                    uint32_t bh[4], bl[4];
                    ldsm_x4(bh, wh + o);
                    ldsm_x4(bl, wl + o);
                    #pragma unroll
                    for (int mt = 0; mt < 2; mt++) {
                        mma16816(acc[mt][2 * pr],     ah[mt], bh);
                        mma16816(acc[mt][2 * pr + 1], ah[mt], bh + 2);
                    }
                    #pragma unroll
                    for (int mt = 0; mt < 2; mt++) {
                        mma16816(acc[mt][2 * pr],     ah[mt], bl);
                        mma16816(acc[mt][2 * pr + 1], ah[mt], bl + 2);
                    }
                    #pragma unroll
                    for (int mt = 0; mt < 2; mt++) {
                        mma16816(acc[mt][2 * pr],     al[mt], bh);
                        mma16816(acc[mt][2 * pr + 1], al[mt], bh + 2);
                    }
                }
            }

            if (layer == 0) {
                __syncthreads();   // all warps done reading X
                // bias + ELU -> split back into Xhi/Xlo as layer-2 A
                const float* b1s = (const float*)(sm + SM_B1);
                #pragma unroll
                for (int mt = 0; mt < 2; mt++) {
                    const int r0 = wrow + mt * 16 + (lane >> 2);
                    #pragma unroll
                    for (int nt = 0; nt < 8; nt++) {
                        const int c  = wcol + nt * 8 + (lane & 3) * 2;
                        const float bb0 = b1s[c], bb1 = b1s[c + 1];
                        float e0 = elu_f(acc[mt][nt][0] + bb0);
                        float e1 = elu_f(acc[mt][nt][1] + bb1);
                        float e2 = elu_f(acc[mt][nt][2] + bb0);
                        float e3 = elu_f(acc[mt][nt][3] + bb1);
                        uint32_t h0, l0, h1, l1;
                        split_bf16(e0, e1, h0, l0);
                        split_bf16(e2, e3, h1, l1);
                        const uint32_t o0 = soff(r0, c);
                        const uint32_t o1 = soff(r0 + 8, c);
                        *(uint32_t*)(sm + SM_XHI + o0) = h0;
                        *(uint32_t*)(sm + SM_XLO + o0) = l0;
                        *(uint32_t*)(sm + SM_XHI + o1) = h1;
                        *(uint32_t*)(sm + SM_XLO + o1) = l1;
                        acc[mt][nt][0] = 0.0f; acc[mt][nt][1] = 0.0f;
                        acc[mt][nt][2] = 0.0f; acc[mt][nt][3] = 0.0f;
                    }
                }
                __syncthreads();
            }
        }

        __syncthreads();   // all warps done reading X before scratch reuse

        // ---- epilogue 2: bias + ELU + weight -> scratch ----
        {
            const float* b2s  = (const float*)(sm + SM_B2);
            const float* roww = (const float*)(sm + SM_ROWW);
            float* scr = (float*)(sm + SM_SCR);
            #pragma unroll
            for (int mt = 0; mt < 2; mt++) {
                const int r0 = wrow + mt * 16 + (lane >> 2);
                const int r1 = r0 + 8;
                const float w0 = roww[r0], w1 = roww[r1];
                #pragma unroll
                for (int nt = 0; nt < 8; nt++) {
                    const int c  = wcol + nt * 8 + (lane & 3) * 2;
                    const float bb0 = b2s[c], bb1 = b2s[c + 1];
                    float2 p0, p1;
                    p0.x = w0 * elu_f(acc[mt][nt][0] + bb0);
                    p0.y = w0 * elu_f(acc[mt][nt][1] + bb1);
                    p1.x = w1 * elu_f(acc[mt][nt][2] + bb0);
                    p1.y = w1 * elu_f(acc[mt][nt][3] + bb1);
                    *(float2*)&scr[(size_t)r0 * 132 + c] = p0;
                    *(float2*)&scr[(size_t)r1 * 132 + c] = p1;
                }
            }
        }
        __syncthreads();

        // ---- 16-row weighted reduce -> out ----
        {
            const int q  = tid >> 5;         // 0..7
            const int c0 = (tid & 31) * 4;   // 0..124
            const float* scr = (const float*)(sm + SM_SCR);
            float4 a4 = make_float4(0.f, 0.f, 0.f, 0.f);
            #pragma unroll
            for (int i = 0; i < 16; i++) {
                const float4 v = *(const float4*)&scr[(size_t)(q * 16 + i) * 132 + c0];
                a4.x += v.x; a4.y += v.y; a4.z += v.z; a4.w += v.w;
            }
            *(float4*)&out[(size_t)(qbase + q) * 128 + c0] = a4;
        }
        __syncthreads();
    }
}

extern "C" void kernel_launch(void* const* d_in, const int* in_sizes, int n_in,
                              void* d_out, int out_size) {
    const float* f1     = (const float*)d_in[0];
    const float* f2     = (const float*)d_in[1];
    const float* x1     = (const float*)d_in[2];
    const float* x2     = (const float*)d_in[3];
    const void*  topk   = d_in[6];
    const float* W1     = (const float*)d_in[7];
    const float* b1     = (const float*)d_in[8];
    const float* W2     = (const float*)d_in[9];
    const float* b2     = (const float*)d_in[10];
    const float* radius = (const float*)d_in[11];
    float* out = (float*)d_out;

    prep_w_kernel<<<128, 256>>>(W1, W2);

    cudaFuncSetAttribute(fused_mma_kernel,
                         cudaFuncAttributeMaxDynamicSharedMemorySize, SM_TOTAL);
    fused_mma_kernel<<<kGrid, kThreads, SM_TOTAL>>>(
        f1, f2, x1, x2, topk, b1, b2, radius, out);
}

// round 5
// speedup vs baseline: 3.5889x; 2.2726x over previous
#include <cuda_runtime.h>
#include <cuda_fp16.h>
#include <cstdint>

// fp16 2-pass "exact-A" tensor-core version (mma.sync m16n8k16 f16, sm_80 PTX).
//   X[128x128] = [features2[topk] | features1]  (8 queries x 16 nbrs = 128 rows)
//   H = ELU(X@W1+b1); Y = ELU(H@W2+b2); out[q] = sum_k w[q,k] * Y[q*16+k]
// GEMM: D(fp32) = Xh*Wh + Xl*Wh = (Xh+Xl)*Wh = X*Wh  (A exact; err = W fp16 rounding)

namespace {
constexpr int kN1      = 50000;
constexpr int kNN      = 16;
constexpr int kQPB     = 8;
constexpr int kTiles   = kN1 / kQPB;   // 6250
constexpr int kThreads = 256;
constexpr int kGrid    = 148;

// SMEM byte offsets
constexpr int SM_ROWW  = 0;            // 128 f32
constexpr int SM_B1    = 512;          // 128 f32
constexpr int SM_B2    = 1024;         // 128 f32
constexpr int SM_X     = 2048;         // 128 rows x 256 fp16 (kk<128: hi, >=128: lo)
constexpr int SM_W     = SM_X + 128 * 512;       // 67584; 2 layers x 32768 B
constexpr int SM_WSZ   = 32768;
constexpr int SM_TOTAL = SM_W + 2 * SM_WSZ;      // 133120 B
}

// fp16 weights, transposed+swizzled: [W1, W2], each [n][k]
__device__ __align__(16) unsigned char g_Wh[2 * SM_WSZ];

// X tile: row stride 512 B, XOR swizzle on 16B groups within 128B lines
__device__ __forceinline__ uint32_t soff(int r, int kk) {
    return (uint32_t)(r * 512 + (((kk >> 3) ^ (r & 7)) << 4) + (kk & 7) * 2);
}
// W tile: row stride 256 B
__device__ __forceinline__ uint32_t woff(int n, int k) {
    return (uint32_t)(n * 256 + (((k >> 3) ^ (n & 7)) << 4) + (k & 7) * 2);
}

__device__ __forceinline__ uint32_t smem_u32(const void* p) {
    uint32_t a;
    asm("{ .reg .u64 t; cvta.to.shared.u64 t, %1; cvt.u32.u64 %0, t; }"
        : "=r"(a) : "l"(p));
    return a;
}
__device__ __forceinline__ void ldsm_x4(uint32_t* r, uint32_t addr) {
    asm volatile("ldmatrix.sync.aligned.m8n8.x4.shared.b16 {%0,%1,%2,%3}, [%4];"
                 : "=r"(r[0]), "=r"(r[1]), "=r"(r[2]), "=r"(r[3]) : "r"(addr));
}
__device__ __forceinline__ void mma16816(float* d, const uint32_t* a,
                                         const uint32_t* b) {
    asm volatile(
        "mma.sync.aligned.m16n8k16.row.col.f32.f16.f16.f32 "
        "{%0,%1,%2,%3}, {%4,%5,%6,%7}, {%8,%9}, {%0,%1,%2,%3};"
        : "+f"(d[0]), "+f"(d[1]), "+f"(d[2]), "+f"(d[3])
        : "r"(a[0]), "r"(a[1]), "r"(a[2]), "r"(a[3]), "r"(b[0]), "r"(b[1]));
}
__device__ __forceinline__ float elu_f(float x) {
    return x > 0.0f ? x : (__expf(x) - 1.0f);
}
// exact fp16 hi/lo split of a float pair -> two packed half2
__device__ __forceinline__ void split_h2(float a, float b, uint32_t& hi,
                                         uint32_t& lo) {
    const __half ah = __float2half_rn(a);
    const __half bh = __float2half_rn(b);
    __half2 h2 = __halves2half2(ah, bh);
    __half2 l2 = __halves2half2(__float2half_rn(a - __half2float(ah)),
                                __float2half_rn(b - __half2float(bh)));
    hi = *(uint32_t*)&h2;
    lo = *(uint32_t*)&l2;
}

// ---------------- W prep kernel ----------------
__global__ void prep_w_kernel(const float* __restrict__ W1,
                              const float* __restrict__ W2) {
    int idx = blockIdx.x * blockDim.x + threadIdx.x;   // 0 .. 32767
    if (idx >= 2 * 128 * 128) return;
    int l = idx >> 14;
    int e = idx & 16383;
    int n = e >> 7;      // output channel (B row)
    int k = e & 127;     // contraction
    const float* W = l ? W2 : W1;
    float v = W[k * 128 + n];                       // B[n][k] = W[k][n]
    *(__half*)(g_Wh + l * SM_WSZ + woff(n, k)) = __float2half_rn(v);
}

// issue the gather LDGs for one tile into registers
__device__ __forceinline__ void gather_regs(int tile, int tid, bool is64,
                                            const float* __restrict__ f1,
                                            const float* __restrict__ f2,
                                            const void* __restrict__ topk,
                                            float4 pf[8][2]) {
    const int qb = tile * kQPB;
    const int g  = tid & 15;           // 8-float group per row
    #pragma unroll
    for (int it = 0; it < 8; ++it) {
        const int rr = (tid >> 4) + it * 16;       // row 0..127
        const int q  = qb + (rr >> 4);
        const float4* p;
        if (g < 8) {
            const int nb = rr & 15;
            const int gi = is64 ? (int)((const long long*)topk)[q * kNN + nb]
                                : ((const int*)topk)[q * kNN + nb];
            p = (const float4*)(f2 + (size_t)gi * 64) + g * 2;
        } else {
            p = (const float4*)(f1 + (size_t)q * 64) + (g - 8) * 2;
        }
        pf[it][0] = p[0];
        pf[it][1] = p[1];
    }
}

// ---------------- main persistent kernel ----------------
__global__ void __launch_bounds__(kThreads, 1)
fused_mma_kernel(const float* __restrict__ f1, const float* __restrict__ f2,
                 const float* __restrict__ x1, const float* __restrict__ x2,
                 const void* __restrict__ topk,
                 const float* __restrict__ b1, const float* __restrict__ b2,
                 const float* __restrict__ radius, float* __restrict__ out)
{
    extern __shared__ char sm[];
    const uint32_t smb = smem_u32(sm);
    const int tid  = threadIdx.x;
    const int wid  = tid >> 5;
    const int lane = tid & 31;
    __shared__ int s_is64;

    // stage fp16 weights into SMEM once
    {
        const float4* src = (const float4*)g_Wh;
        float4* dst = (float4*)(sm + SM_W);
        #pragma unroll
        for (int i = 0; i < 16; i++) dst[tid + i * 256] = src[tid + i * 256];
    }
    if (tid < 128) {
        ((float*)(sm + SM_B1))[tid] = b1[tid];
        ((float*)(sm + SM_B2))[tid] = b2[tid];
    }
    if (tid < 32) {
        const int* t32 = (const int*)topk;
        unsigned m = __ballot_sync(0xFFFFFFFFu, t32[2 * tid + 1] != 0);
        if (tid == 0) s_is64 = (m == 0u) ? 1 : 0;
    }
    __syncthreads();

    const bool  is64 = (s_is64 != 0);
    const float r    = radius[0];
    const float nid  = -1.0f / (2.0f * r * r);

    const int wrow = (wid & 3) * 32;   // warp tile rows [wrow, wrow+32)
    const int wcol = (wid >> 2) * 64;  // warp tile cols [wcol, wcol+64)
    const int mat  = lane >> 3;        // ldmatrix sub-matrix index
    const int mrow = lane & 7;

    const uint32_t xb = smb + SM_X;

    // prologue: gather tile 0 (this CTA's first tile) into registers
    float4 pf[8][2];
    gather_regs(blockIdx.x, tid, is64, f1, f2, topk, pf);

    for (int tile = blockIdx.x; tile < kTiles; tile += gridDim.x) {
        const int qbase = tile * kQPB;

        __syncthreads();   // prev tile's layer-2 MMA done: X safe to overwrite

        // ---- convert prefetched registers -> Xhi/Xlo halves in smem ----
        {
            const int g = tid & 15;
            #pragma unroll
            for (int it = 0; it < 8; ++it) {
                const int rr = (tid >> 4) + it * 16;
                const float v[8] = {pf[it][0].x, pf[it][0].y, pf[it][0].z, pf[it][0].w,
                                    pf[it][1].x, pf[it][1].y, pf[it][1].z, pf[it][1].w};
                uint4 hi4, lo4;
                uint32_t* hp = (uint32_t*)&hi4;
                uint32_t* lp = (uint32_t*)&lo4;
                #pragma unroll
                for (int j = 0; j < 4; j++)
                    split_h2(v[2 * j], v[2 * j + 1], hp[j], lp[j]);
                *(uint4*)(sm + SM_X + soff(rr, g * 8))       = hi4;
                *(uint4*)(sm + SM_X + soff(rr, g * 8 + 128)) = lo4;
            }
        }
        // ---- per-row distance weights ----
        if (tid < 128) {
            const int q  = qbase + (tid >> 4);
            const int kk = tid & 15;
            int gi = is64 ? (int)((const long long*)topk)[q * kNN + kk]
                          : ((const int*)topk)[q * kNN + kk];
            const float dx = x2[gi * 3 + 0] - x1[q * 3 + 0];
            const float dy = x2[gi * 3 + 1] - x1[q * 3 + 1];
            const float dz = x2[gi * 3 + 2] - x1[q * 3 + 2];
            const float w  = __expf(nid * (dx * dx + dy * dy + dz * dz));
            ((float*)(sm + SM_ROWW))[tid] = (gi == 0) ? 0.0f : w;
        }
        __syncthreads();

        // ---- issue next tile's gather LDGs (hidden under MMA below) ----
        const int nxt = tile + gridDim.x;
        if (nxt < kTiles) gather_regs(nxt, tid, is64, f1, f2, topk, pf);

        float acc[2][8][4];
        #pragma unroll
        for (int i = 0; i < 2; i++)
            #pragma unroll
            for (int j = 0; j < 8; j++)
                #pragma unroll
                for (int e = 0; e < 4; e++) acc[i][j][e] = 0.0f;

        #pragma unroll 1
        for (int layer = 0; layer < 2; ++layer) {
            const uint32_t wb = smb + SM_W + layer * SM_WSZ;

            #pragma unroll 1
            for (int ks = 0; ks < 8; ++ks) {
                // B fragments once per ks, reused by both A halves
                uint32_t bfr[4][4];
                #pragma unroll
                for (int pr = 0; pr < 4; pr++) {
                    const int n  = wcol + pr * 16 + (mat >> 1) * 8 + mrow;
                    const int kk = ks * 16 + (mat & 1) * 8;
                    ldsm_x4(bfr[pr], wb + woff(n, kk));
                }
                #pragma unroll
                for (int hv = 0; hv < 2; hv++) {   // 0: Xhi, 1: Xlo
                    uint32_t afr[2][4];
                    #pragma unroll
                    for (int mt = 0; mt < 2; mt++) {
                        const int row = wrow + mt * 16 + (mat & 1) * 8 + mrow;
                        const int kk  = ks * 16 + hv * 128 + (mat >> 1) * 8;
                        ldsm_x4(afr[mt], xb + soff(row, kk));
                    }
                    #pragma unroll
                    for (int pr = 0; pr < 4; pr++) {
                        #pragma unroll
                        for (int mt = 0; mt < 2; mt++) {
                            mma16816(acc[mt][2 * pr],     afr[mt], bfr[pr]);
                            mma16816(acc[mt][2 * pr + 1], afr[mt], bfr[pr] + 2);
                        }
                    }
                }
            }

            if (layer == 0) {
                __syncthreads();   // all warps done reading X
                // bias + ELU -> exact fp16 split back into X as layer-2 A
                const float* b1s = (const float*)(sm + SM_B1);
                #pragma unroll
                for (int mt = 0; mt < 2; mt++) {
                    const int r0 = wrow + mt * 16 + (lane >> 2);
                    #pragma unroll
                    for (int nt = 0; nt < 8; nt++) {
                        const int c  = wcol + nt * 8 + (lane & 3) * 2;
                        const float bb0 = b1s[c], bb1 = b1s[c + 1];
                        float e0 = elu_f(acc[mt][nt][0] + bb0);
                        float e1 = elu_f(acc[mt][nt][1] + bb1);
                        float e2 = elu_f(acc[mt][nt][2] + bb0);
                        float e3 = elu_f(acc[mt][nt][3] + bb1);
                        uint32_t h0, l0, h1, l1;
                        split_h2(e0, e1, h0, l0);
                        split_h2(e2, e3, h1, l1);
                        *(uint32_t*)(sm + SM_X + soff(r0, c))           = h0;
                        *(uint32_t*)(sm + SM_X + soff(r0, c + 128))     = l0;
                        *(uint32_t*)(sm + SM_X + soff(r0 + 8, c))       = h1;
                        *(uint32_t*)(sm + SM_X + soff(r0 + 8, c + 128)) = l1;
                        acc[mt][nt][0] = 0.0f; acc[mt][nt][1] = 0.0f;
                        acc[mt][nt][2] = 0.0f; acc[mt][nt][3] = 0.0f;
                    }
                }
                __syncthreads();
            }
        }

        // ---- epilogue 2: bias + ELU + weighted 16-row reduce via shuffles ----
        {
            const float* b2s  = (const float*)(sm + SM_B2);
            const float* roww = (const float*)(sm + SM_ROWW);
            #pragma unroll
            for (int mt = 0; mt < 2; mt++) {
                const int q  = (wrow >> 4) + mt;          // query in [0,8)
                const int r0 = wrow + mt * 16 + (lane >> 2);
                const float w0 = roww[r0], w1 = roww[r0 + 8];
                #pragma unroll
                for (int nt = 0; nt < 8; nt++) {
                    const int c  = wcol + nt * 8 + (lane & 3) * 2;
                    const float bb0 = b2s[c], bb1 = b2s[c + 1];
                    float s0 = w0 * elu_f(acc[mt][nt][0] + bb0)
                             + w1 * elu_f(acc[mt][nt][2] + bb0);
                    float s1 = w0 * elu_f(acc[mt][nt][1] + bb1)
                             + w1 * elu_f(acc[mt][nt][3] + bb1);
                    s0 += __shfl_xor_sync(0xFFFFFFFFu, s0, 4);
                    s1 += __shfl_xor_sync(0xFFFFFFFFu, s1, 4);
                    s0 += __shfl_xor_sync(0xFFFFFFFFu, s0, 8);
                    s1 += __shfl_xor_sync(0xFFFFFFFFu, s1, 8);
                    s0 += __shfl_xor_sync(0xFFFFFFFFu, s0, 16);
                    s1 += __shfl_xor_sync(0xFFFFFFFFu, s1, 16);
                    if ((lane >> 2) == 0) {
                        float2 o2 = make_float2(s0, s1);
                        *(float2*)&out[(size_t)(qbase + q) * 128 + c] = o2;
                    }
                }
            }
        }
    }
}

extern "C" void kernel_launch(void* const* d_in, const int* in_sizes, int n_in,
                              void* d_out, int out_size) {
    const float* f1     = (const float*)d_in[0];
    const float* f2     = (const float*)d_in[1];
    const float* x1     = (const float*)d_in[2];
    const float* x2     = (const float*)d_in[3];
    const void*  topk   = d_in[6];
    const float* W1     = (const float*)d_in[7];
    const float* b1     = (const float*)d_in[8];
    const float* W2     = (const float*)d_in[9];
    const float* b2     = (const float*)d_in[10];
    const float* radius = (const float*)d_in[11];
    float* out = (float*)d_out;

    prep_w_kernel<<<128, 256>>>(W1, W2);

    cudaFuncSetAttribute(fused_mma_kernel,
                         cudaFuncAttributeMaxDynamicSharedMemorySize, SM_TOTAL);
    fused_mma_kernel<<<kGrid, kThreads, SM_TOTAL>>>(
        f1, f2, x1, x2, topk, b1, b2, radius, out);
}